// round 4
// baseline (speedup 1.0000x reference)
#include <cuda_runtime.h>

// Problem constants (fixed by setup_inputs: audio (8, 80000) fp32)
#define BATCH   8
#define TLEN    80000
#define KFRM    250
#define FRAME   320
#define LAGS    189
#define LAG_MIN 5
#define HALFSZ  94             // LAGS // 2
#define SEGLEN  509            // FRAME + LAGS
#define NOUT    235
#define WINMED  30
#define PADM    14
#define EPSF    1e-9f

// nccf kernel blocking
#define TPF   24               // lag-groups per frame (8 lags each, 192 padded)
#define KSPL  4                // split-K factor (threads per lag-group)
#define FPB   4                // frames per block
#define NTHR  (FPB * TPF * KSPL)   // 384 threads, 12 warps
#define NLAGP 192
#define SEGL  520              // logical padded segment length
#define SEGP  584              // physical (skewed) words per frame

// output layout (float32): f0[B*NOUT], whiten[B*NOUT], voiced[B*NOUT], energy[B*KFRM]
#define OFF_F0     0
#define OFF_WHITEN (BATCH * NOUT)
#define OFF_VOICED (2 * BATCH * NOUT)
#define OFF_ENERGY (3 * BATCH * NOUT)

__device__ int g_idx[BATCH * KFRM];

typedef unsigned long long ull;

__device__ __forceinline__ int skew(int m) { return m + ((m >> 5) << 2); }

__device__ __forceinline__ ull pk(float lo, float hi) {
    ull r; asm("mov.b64 %0, {%1, %2};" : "=l"(r) : "f"(lo), "f"(hi)); return r;
}
__device__ __forceinline__ void upk(float& lo, float& hi, ull v) {
    asm("mov.b64 {%0, %1}, %2;" : "=f"(lo), "=f"(hi) : "l"(v));
}
__device__ __forceinline__ void ffma2(ull& d, ull a, ull b) {
    asm("fma.rn.f32x2 %0, %1, %2, %0;" : "+l"(d) : "l"(a), "l"(b));
}

// ---------------------------------------------------------------------------
// Kernel 1: NCCF + argmax + energy. 4 frames/block, 384 threads.
// Thread (f, g, h): lags 8g..8g+7 over K-chunk h (window steps 20h..20h+19)
// with a sliding register window and packed f32x2 FMAs. The 4 K-partials
// combine via shfl_xor (h = tid&3 -> partners in-warp). Norms from one
// running sum + endpoint fixups.
// ---------------------------------------------------------------------------
__global__ void __launch_bounds__(NTHR) nccf_kernel(const float* __restrict__ audio,
                                                    float* __restrict__ out) {
    __shared__ __align__(16) float seg[FPB][SEGP];
    __shared__ float sval[FPB][NLAGP];

    const int tid  = threadIdx.x;
    const int warp = tid >> 5;
    const int lane = tid & 31;
    const int fr0  = blockIdx.x * FPB;

    // Stage: 12 warps, 3 warps per frame (skewed layout, zero-padded)
    {
        const int fr   = warp & 3;
        const int part = warp >> 2;       // 0..2
        const int gfr  = fr0 + fr;
        const int b    = gfr / KFRM;
        const int k    = gfr - b * KFRM;
        const float* row  = audio + (size_t)b * TLEN;
        const int    base = k * FRAME;
        for (int j = part * 32 + lane; j < SEGL; j += 96) {
            float v = 0.0f;
            if (j < SEGLEN && base + j < TLEN) v = row[base + j];
            seg[fr][skew(j)] = v;
        }
    }
    __syncthreads();

    {
        const int h  = tid & 3;                 // K-chunk
        const int gg = tid >> 2;                // 0..95
        const int f  = gg / TPF;
        const int g  = gg - f * TPF;
        const float* sf = seg[f];
        const int gb = 8 * g;
        const int sb = 20 * h;                  // window-step base

        ull c0 = 0, c1 = 0, c2 = 0, c3 = 0, c4 = 0, c5 = 0, c6 = 0, c7 = 0, ns = 0;
        float4 W1;
        ull O0, O1, O2, E1, E2, E3;
        {
            float4 W0 = *reinterpret_cast<const float4*>(sf + skew(gb + 4 * sb));
            W1        = *reinterpret_cast<const float4*>(sf + skew(gb + 4 * sb + 4));
            O0 = pk(W0.y, W0.z); O1 = pk(W0.w, W1.x); O2 = pk(W1.y, W1.z);
            E1 = pk(W0.z, W0.w); E2 = pk(W1.x, W1.y); E3 = pk(W1.z, W1.w);
        }

        #pragma unroll 5
        for (int s = 0; s < 20; s++) {
            float4 Aq = *reinterpret_cast<const float4*>(sf + skew(4 * (sb + s)));
            ull A01 = pk(Aq.x, Aq.y);
            ull A23 = pk(Aq.z, Aq.w);
            float4 W2 = *reinterpret_cast<const float4*>(sf + skew(gb + 8 + 4 * (sb + s)));

            ull O3 = pk(W1.w, W2.x);
            ull E4 = pk(W2.x, W2.y);
            ull O4 = pk(W2.y, W2.z);
            ull E5 = pk(W2.z, W2.w);

            ffma2(c0, A01, O0); ffma2(c0, A23, O1);
            ffma2(c1, A01, E1); ffma2(c1, A23, E2);
            ffma2(c2, A01, O1); ffma2(c2, A23, O2);
            ffma2(c3, A01, E2); ffma2(c3, A23, E3);
            ffma2(c4, A01, O2); ffma2(c4, A23, O3);
            ffma2(c5, A01, E3); ffma2(c5, A23, E4);
            ffma2(c6, A01, O3); ffma2(c6, A23, O4);
            ffma2(c7, A01, E4); ffma2(c7, A23, E5);
            ffma2(ns, O0, O0);  ffma2(ns, O1, O1);

            O0 = O2; O1 = O3; O2 = O4;
            E1 = E3; E2 = E4; E3 = E5;
            W1 = W2;
        }

        // Reduce packed pairs to scalars, then combine K-partials via shfl.
        float cr[8], nsum;
        { float lo, hi;
          upk(lo, hi, c0); cr[0] = lo + hi; upk(lo, hi, c1); cr[1] = lo + hi;
          upk(lo, hi, c2); cr[2] = lo + hi; upk(lo, hi, c3); cr[3] = lo + hi;
          upk(lo, hi, c4); cr[4] = lo + hi; upk(lo, hi, c5); cr[5] = lo + hi;
          upk(lo, hi, c6); cr[6] = lo + hi; upk(lo, hi, c7); cr[7] = lo + hi;
          upk(lo, hi, ns); nsum  = lo + hi; }
        #pragma unroll
        for (int d = 1; d <= 2; d <<= 1) {
            #pragma unroll
            for (int l = 0; l < 8; l++)
                cr[l] += __shfl_xor_sync(0xffffffffu, cr[l], d);
            nsum += __shfl_xor_sync(0xffffffffu, nsum, d);
        }

        // norms: n2[0] = nsum, n2[l] via endpoint fixups
        float n2[8];
        n2[0] = nsum;
        #pragma unroll
        for (int l = 1; l < 8; l++) {
            float xa = sf[skew(gb + l)];
            float xb = sf[skew(gb + 320 + l)];
            n2[l] = n2[l - 1] - xa * xa + xb * xb;
        }
        // each h-thread writes 2 of the 8 lags
        #pragma unroll
        for (int l = 2 * h; l < 2 * h + 2; l++) {
            float d = EPSF + sqrtf(n2[l]);
            sval[f][gb + l] = cr[l] / (d * d);
        }

        if (g == 0 && h == 0) {  // energy = (n2[0] + seg[0]^2 - seg[320]^2)/320
            float x0 = sf[skew(0)], x3 = sf[skew(320)];
            out[OFF_ENERGY + fr0 + f] = (n2[0] + x0 * x0 - x3 * x3) * (1.0f / FRAME);
        }
    }
    __syncthreads();

    // Argmax per frame: warps 0..3 handle frames 0..3 (first-occurrence)
    if (warp < FPB) {
        const float* sv = sval[warp];
        float bv = -3.0e38f; int bi = 1 << 30;
        float hv = -3.0e38f; int hi = 1 << 30;
        for (int t = LAG_MIN + lane; t < LAGS; t += 32) {
            float x = sv[t];
            if (x > bv) { bv = x; bi = t; }
            if (t < HALFSZ && x > hv) { hv = x; hi = t; }
        }
        #pragma unroll
        for (int off = 16; off; off >>= 1) {
            float ov  = __shfl_down_sync(0xffffffffu, bv, off);
            int   oi  = __shfl_down_sync(0xffffffffu, bi, off);
            if (ov > bv || (ov == bv && oi < bi)) { bv = ov; bi = oi; }
            float ohv = __shfl_down_sync(0xffffffffu, hv, off);
            int   ohi = __shfl_down_sync(0xffffffffu, hi, off);
            if (ohv > hv || (ohv == hv && ohi < hi)) { hv = ohv; hi = ohi; }
        }
        if (lane == 0) {
            int sel = (hv > 0.99f * bv) ? hi : bi;
            g_idx[fr0 + warp] = sel + 1;
        }
    }
}

// ---------------------------------------------------------------------------
// Kernel 2 (fused, single block): all medians -> f0/voiced, then global
// mean/std + whiten with f0 cached in smem. No cross-block sync needed.
// ---------------------------------------------------------------------------
__global__ void __launch_bounds__(512) median_stats_kernel(float* __restrict__ out) {
    __shared__ int   row[BATCH][256];
    __shared__ float f0s[BATCH * NOUT];
    __shared__ float red[512];
    const int tid = threadIdx.x;
    const int N   = BATCH * NOUT;   // 1880

    for (int t = tid; t < BATCH * KFRM; t += 512)
        row[t / KFRM][t % KFRM] = g_idx[t];
    __syncthreads();

    for (int n = tid; n < N; n += 512) {
        const int b = n / NOUT;
        const int j = n - b * NOUT;
        int w[WINMED];
        #pragma unroll
        for (int m = 0; m < WINMED; m++) {
            int p = j + m - PADM;
            w[m] = row[b][p < 0 ? 0 : p];
        }
        // rank-14 (0-based) = smallest x with count(w <= x) >= 15
        int lo = 1, hi = LAGS + 1;
        #pragma unroll
        for (int it = 0; it < 8; it++) {
            if (lo >= hi) break;
            int mid = (lo + hi) >> 1;
            int cnt = 0;
            #pragma unroll
            for (int m = 0; m < WINMED; m++) cnt += (w[m] <= mid);
            if (cnt >= PADM + 1) hi = mid; else lo = mid + 1;
        }
        float f0 = 16000.0f / (1e-9f + (float)lo);
        f0s[n] = f0;
        out[OFF_F0 + n]     = f0;
        out[OFF_VOICED + n] = 1.0f;   // idx >= 6 -> f0 > 0 always
    }
    __syncthreads();

    // mean
    float s = 0.0f;
    for (int i = tid; i < N; i += 512) s += f0s[i];
    red[tid] = s;
    __syncthreads();
    #pragma unroll
    for (int off = 256; off; off >>= 1) {
        if (tid < off) red[tid] += red[tid + off];
        __syncthreads();
    }
    float mean = red[0] / (float)N;
    __syncthreads();

    // var
    float s2 = 0.0f;
    for (int i = tid; i < N; i += 512) {
        float d = f0s[i] - mean;
        s2 = fmaf(d, d, s2);
    }
    red[tid] = s2;
    __syncthreads();
    #pragma unroll
    for (int off = 256; off; off >>= 1) {
        if (tid < off) red[tid] += red[tid + off];
        __syncthreads();
    }
    float sd = sqrtf(red[0] / (float)(N - 1));
    if (sd == 0.0f) sd = 1.0f;
    float inv = 1.0f / sd;

    for (int i = tid; i < N; i += 512)
        out[OFF_WHITEN + i] = (f0s[i] - mean) * inv;
}

extern "C" void kernel_launch(void* const* d_in, const int* in_sizes, int n_in,
                              void* d_out, int out_size) {
    const float* audio = (const float*)d_in[0];
    float* out = (float*)d_out;
    (void)in_sizes; (void)n_in; (void)out_size;

    nccf_kernel<<<(BATCH * KFRM) / FPB, NTHR>>>(audio, out);
    median_stats_kernel<<<1, 512>>>(out);
}

// round 5
// speedup vs baseline: 1.1618x; 1.1618x over previous
#include <cuda_runtime.h>

// Problem constants (fixed by setup_inputs: audio (8, 80000) fp32)
#define BATCH   8
#define TLEN    80000
#define KFRM    250
#define FRAME   320
#define LAGS    189
#define LAG_MIN 5
#define HALFSZ  94             // LAGS // 2
#define SEGLEN  509            // FRAME + LAGS
#define NOUT    235
#define WINMED  30
#define PADM    14
#define EPSF    1e-9f

// nccf kernel blocking
#define TPF   24               // lag-groups per frame (8 lags each, 192 padded)
#define KSPL  2                // split-K factor (threads per lag-group)
#define FPB   4                // frames per block
#define NTHR  (FPB * TPF * KSPL)   // 192 threads, 6 warps
#define NLAGP 192
#define SEGL  520              // logical padded segment length
#define SEGP  584              // physical (skewed) words per frame

// output layout (float32): f0[B*NOUT], whiten[B*NOUT], voiced[B*NOUT], energy[B*KFRM]
#define OFF_F0     0
#define OFF_WHITEN (BATCH * NOUT)
#define OFF_VOICED (2 * BATCH * NOUT)
#define OFF_ENERGY (3 * BATCH * NOUT)

__device__ int g_idx[BATCH * KFRM];

typedef unsigned long long ull;

__device__ __forceinline__ int skew(int m) { return m + ((m >> 5) << 2); }

__device__ __forceinline__ ull pk(float lo, float hi) {
    ull r; asm("mov.b64 %0, {%1, %2};" : "=l"(r) : "f"(lo), "f"(hi)); return r;
}
__device__ __forceinline__ void upk(float& lo, float& hi, ull v) {
    asm("mov.b64 {%0, %1}, %2;" : "=f"(lo), "=f"(hi) : "l"(v));
}
__device__ __forceinline__ void ffma2(ull& d, ull a, ull b) {
    asm("fma.rn.f32x2 %0, %1, %2, %0;" : "+l"(d) : "l"(a), "l"(b));
}

// ---------------------------------------------------------------------------
// Kernel 1: NCCF + argmax + energy. 4 frames/block, 192 threads, grid 500
// (single wave: 500 blocks < 148 SMs x 5 resident). Thread (f, g, h):
// lags 8g..8g+7 over K-half h (window steps 40h..40h+39) with a sliding
// register window and packed f32x2 FMAs; the 2 K-partials combine via one
// shfl_xor round. Norms via one running sum + endpoint fixups.
// ---------------------------------------------------------------------------
__global__ void __launch_bounds__(NTHR) nccf_kernel(const float* __restrict__ audio,
                                                    float* __restrict__ out) {
    __shared__ __align__(16) float seg[FPB][SEGP];
    __shared__ float sval[FPB][NLAGP];

    const int tid  = threadIdx.x;
    const int warp = tid >> 5;
    const int lane = tid & 31;
    const int fr0  = blockIdx.x * FPB;

    // Stage 4 frames flat across 192 threads (skewed layout, zero-padded)
    for (int idx = tid; idx < FPB * SEGL; idx += NTHR) {
        const int fr = idx / SEGL;
        const int j  = idx - fr * SEGL;
        const int gfr = fr0 + fr;
        const int b   = gfr / KFRM;
        const int k   = gfr - b * KFRM;
        float v = 0.0f;
        const int src = k * FRAME + j;
        if (j < SEGLEN && src < TLEN) v = audio[(size_t)b * TLEN + src];
        seg[fr][skew(j)] = v;
    }
    __syncthreads();

    {
        const int h  = tid & 1;                 // K-half
        const int gg = tid >> 1;                // 0..95
        const int f  = gg / TPF;
        const int g  = gg - f * TPF;
        const float* sf = seg[f];
        const int gb = 8 * g;
        const int sb = 40 * h;                  // window-step base

        ull c0 = 0, c1 = 0, c2 = 0, c3 = 0, c4 = 0, c5 = 0, c6 = 0, c7 = 0, ns = 0;
        float4 W1;
        ull O0, O1, O2, E1, E2, E3;
        {
            float4 W0 = *reinterpret_cast<const float4*>(sf + skew(gb + 4 * sb));
            W1        = *reinterpret_cast<const float4*>(sf + skew(gb + 4 * sb + 4));
            O0 = pk(W0.y, W0.z); O1 = pk(W0.w, W1.x); O2 = pk(W1.y, W1.z);
            E1 = pk(W0.z, W0.w); E2 = pk(W1.x, W1.y); E3 = pk(W1.z, W1.w);
        }

        #pragma unroll 4
        for (int s = 0; s < 40; s++) {
            float4 Aq = *reinterpret_cast<const float4*>(sf + skew(4 * (sb + s)));
            ull A01 = pk(Aq.x, Aq.y);
            ull A23 = pk(Aq.z, Aq.w);
            float4 W2 = *reinterpret_cast<const float4*>(sf + skew(gb + 8 + 4 * (sb + s)));

            ull O3 = pk(W1.w, W2.x);
            ull E4 = pk(W2.x, W2.y);
            ull O4 = pk(W2.y, W2.z);
            ull E5 = pk(W2.z, W2.w);

            ffma2(c0, A01, O0); ffma2(c0, A23, O1);
            ffma2(c1, A01, E1); ffma2(c1, A23, E2);
            ffma2(c2, A01, O1); ffma2(c2, A23, O2);
            ffma2(c3, A01, E2); ffma2(c3, A23, E3);
            ffma2(c4, A01, O2); ffma2(c4, A23, O3);
            ffma2(c5, A01, E3); ffma2(c5, A23, E4);
            ffma2(c6, A01, O3); ffma2(c6, A23, O4);
            ffma2(c7, A01, E4); ffma2(c7, A23, E5);
            ffma2(ns, O0, O0);  ffma2(ns, O1, O1);

            O0 = O2; O1 = O3; O2 = O4;
            E1 = E3; E2 = E4; E3 = E5;
            W1 = W2;
        }

        // Reduce packed pairs to scalars; combine the 2 K-partials via shfl.
        float cr[8], nsum;
        { float lo, hi;
          upk(lo, hi, c0); cr[0] = lo + hi; upk(lo, hi, c1); cr[1] = lo + hi;
          upk(lo, hi, c2); cr[2] = lo + hi; upk(lo, hi, c3); cr[3] = lo + hi;
          upk(lo, hi, c4); cr[4] = lo + hi; upk(lo, hi, c5); cr[5] = lo + hi;
          upk(lo, hi, c6); cr[6] = lo + hi; upk(lo, hi, c7); cr[7] = lo + hi;
          upk(lo, hi, ns); nsum  = lo + hi; }
        #pragma unroll
        for (int l = 0; l < 8; l++)
            cr[l] += __shfl_xor_sync(0xffffffffu, cr[l], 1);
        nsum += __shfl_xor_sync(0xffffffffu, nsum, 1);

        // norms: n2[0] = nsum, n2[l] via endpoint fixups
        float n2[8];
        n2[0] = nsum;
        #pragma unroll
        for (int l = 1; l < 8; l++) {
            float xa = sf[skew(gb + l)];
            float xb = sf[skew(gb + 320 + l)];
            n2[l] = n2[l - 1] - xa * xa + xb * xb;
        }
        // each h-thread writes 4 of the 8 lags (fast rcp: feeds comparisons only)
        #pragma unroll
        for (int l = 4 * h; l < 4 * h + 4; l++) {
            float d = EPSF + sqrtf(n2[l]);
            sval[f][gb + l] = __fdividef(cr[l], d * d);
        }

        if (g == 0 && h == 0) {  // energy = (n2[0] + seg[0]^2 - seg[320]^2)/320
            float x0 = sf[skew(0)], x3 = sf[skew(320)];
            out[OFF_ENERGY + fr0 + f] = (n2[0] + x0 * x0 - x3 * x3) * (1.0f / FRAME);
        }
    }
    __syncthreads();

    // Argmax per frame: warps 0..3 handle frames 0..3 (first-occurrence)
    if (warp < FPB) {
        const float* sv = sval[warp];
        float bv = -3.0e38f; int bi = 1 << 30;
        float hv = -3.0e38f; int hi = 1 << 30;
        for (int t = LAG_MIN + lane; t < LAGS; t += 32) {
            float x = sv[t];
            if (x > bv) { bv = x; bi = t; }
            if (t < HALFSZ && x > hv) { hv = x; hi = t; }
        }
        #pragma unroll
        for (int off = 16; off; off >>= 1) {
            float ov  = __shfl_down_sync(0xffffffffu, bv, off);
            int   oi  = __shfl_down_sync(0xffffffffu, bi, off);
            if (ov > bv || (ov == bv && oi < bi)) { bv = ov; bi = oi; }
            float ohv = __shfl_down_sync(0xffffffffu, hv, off);
            int   ohi = __shfl_down_sync(0xffffffffu, hi, off);
            if (ohv > hv || (ohv == hv && ohi < hi)) { hv = ohv; hi = ohi; }
        }
        if (lane == 0) {
            int sel = (hv > 0.99f * bv) ? hi : bi;
            g_idx[fr0 + warp] = sel + 1;
        }
    }
}

// ---------------------------------------------------------------------------
// Kernel 2: sliding lower-median (rank 14 of 30). NO register window array
// (avoids local-memory spill): left-pad the smem row by PADM and count
// directly from smem in the binary search (8 x 30 conflict-free LDS).
// ---------------------------------------------------------------------------
__global__ void __launch_bounds__(256) median_kernel(float* __restrict__ out) {
    const int b = blockIdx.x;
    __shared__ int row[PADM + KFRM];
    for (int t = threadIdx.x; t < PADM + KFRM; t += 256) {
        int p = t - PADM;
        row[t] = g_idx[b * KFRM + (p < 0 ? 0 : p)];
    }
    __syncthreads();

    const int j = threadIdx.x;
    if (j < NOUT) {
        const int* w = row + j;
        // rank-14 (0-based) = smallest x with count(w <= x) >= 15
        int lo = 1, hi = LAGS + 1;   // width 189 -> 8 halvings reach 0
        #pragma unroll
        for (int it = 0; it < 8; it++) {
            int mid = (lo + hi) >> 1;
            int cnt = 0;
            #pragma unroll
            for (int m = 0; m < WINMED; m++) cnt += (w[m] <= mid);
            if (cnt >= PADM + 1) hi = mid; else lo = mid + 1;
        }
        float f0 = 16000.0f / (1e-9f + (float)lo);
        out[OFF_F0 + b * NOUT + j]     = f0;
        out[OFF_VOICED + b * NOUT + j] = 1.0f;   // idx >= 6 -> f0 > 0 always
    }
}

// ---------------------------------------------------------------------------
// Kernel 3: global mean/std over all f0 (two-pass, matches reference), whiten.
// ---------------------------------------------------------------------------
__global__ void __launch_bounds__(512) stats_kernel(float* __restrict__ out) {
    const int N = BATCH * NOUT;   // 1880
    __shared__ float red[512];
    __shared__ float f0s[BATCH * NOUT];
    const int tid = threadIdx.x;

    float s = 0.0f;
    for (int i = tid; i < N; i += 512) {
        float v = out[OFF_F0 + i];
        f0s[i] = v;
        s += v;
    }
    red[tid] = s;
    __syncthreads();
    #pragma unroll
    for (int off = 256; off; off >>= 1) {
        if (tid < off) red[tid] += red[tid + off];
        __syncthreads();
    }
    float mean = red[0] / (float)N;
    __syncthreads();

    float s2 = 0.0f;
    for (int i = tid; i < N; i += 512) {
        float d = f0s[i] - mean;
        s2 = fmaf(d, d, s2);
    }
    red[tid] = s2;
    __syncthreads();
    #pragma unroll
    for (int off = 256; off; off >>= 1) {
        if (tid < off) red[tid] += red[tid + off];
        __syncthreads();
    }
    float sd = sqrtf(red[0] / (float)(N - 1));
    if (sd == 0.0f) sd = 1.0f;
    float inv = 1.0f / sd;

    for (int i = tid; i < N; i += 512)
        out[OFF_WHITEN + i] = (f0s[i] - mean) * inv;
}

extern "C" void kernel_launch(void* const* d_in, const int* in_sizes, int n_in,
                              void* d_out, int out_size) {
    const float* audio = (const float*)d_in[0];
    float* out = (float*)d_out;
    (void)in_sizes; (void)n_in; (void)out_size;

    nccf_kernel<<<(BATCH * KFRM) / FPB, NTHR>>>(audio, out);
    median_kernel<<<BATCH, 256>>>(out);
    stats_kernel<<<1, 512>>>(out);
}

// round 6
// speedup vs baseline: 1.1722x; 1.0089x over previous
#include <cuda_runtime.h>

// Problem constants (fixed by setup_inputs: audio (8, 80000) fp32)
#define BATCH   8
#define TLEN    80000
#define KFRM    250
#define FRAME   320
#define LAGS    189
#define LAG_MIN 5
#define HALFSZ  94             // LAGS // 2
#define SEGLEN  509            // FRAME + LAGS
#define NOUT    235
#define WINMED  30
#define PADM    14
#define EPSF    1e-9f

// nccf kernel blocking
#define TPF   24               // lag-groups per frame (8 lags each, 192 padded)
#define KSPL  4                // split-K factor (threads per lag-group)
#define FPB   4                // frames per block
#define NTHR  (FPB * TPF * KSPL)   // 384 threads, 12 warps
#define NLAGP 192
#define SEGL  520              // logical padded segment length
#define SEGP  584              // physical (skewed) words per frame

// output layout (float32): f0[B*NOUT], whiten[B*NOUT], voiced[B*NOUT], energy[B*KFRM]
#define OFF_F0     0
#define OFF_WHITEN (BATCH * NOUT)
#define OFF_VOICED (2 * BATCH * NOUT)
#define OFF_ENERGY (3 * BATCH * NOUT)

__device__ int g_idx[BATCH * KFRM];

typedef unsigned long long ull;

__device__ __forceinline__ int skew(int m) { return m + ((m >> 5) << 2); }

__device__ __forceinline__ ull pk(float lo, float hi) {
    ull r; asm("mov.b64 %0, {%1, %2};" : "=l"(r) : "f"(lo), "f"(hi)); return r;
}
__device__ __forceinline__ void upk(float& lo, float& hi, ull v) {
    asm("mov.b64 {%0, %1}, %2;" : "=f"(lo), "=f"(hi) : "l"(v));
}
__device__ __forceinline__ void ffma2(ull& d, ull a, ull b) {
    asm("fma.rn.f32x2 %0, %1, %2, %0;" : "+l"(d) : "l"(a), "l"(b));
}

// ---------------------------------------------------------------------------
// Kernel 1: NCCF + argmax + energy. 4 frames/block, 384 threads, grid 500.
// __launch_bounds__(384,4): 4 blocks/SM -> 592 slots >= 500 blocks = ONE wave.
// Thread (f, g, h): lags 8g..8g+7 over K-chunk h (window steps 20h..20h+19)
// with a sliding register window and packed f32x2 FMAs; the 4 K-partials
// combine via 2 shfl_xor rounds. Norms via one running sum + endpoint fixups.
// ---------------------------------------------------------------------------
__global__ void __launch_bounds__(NTHR, 4) nccf_kernel(const float* __restrict__ audio,
                                                       float* __restrict__ out) {
    __shared__ __align__(16) float seg[FPB][SEGP];
    __shared__ float sval[FPB][NLAGP];

    const int tid  = threadIdx.x;
    const int warp = tid >> 5;
    const int lane = tid & 31;
    const int fr0  = blockIdx.x * FPB;

    // Stage: 12 warps, 3 warps per frame (skewed layout, zero-padded)
    {
        const int fr   = warp & 3;
        const int part = warp >> 2;       // 0..2
        const int gfr  = fr0 + fr;
        const int b    = gfr / KFRM;
        const int k    = gfr - b * KFRM;
        const float* row  = audio + (size_t)b * TLEN;
        const int    base = k * FRAME;
        for (int j = part * 32 + lane; j < SEGL; j += 96) {
            float v = 0.0f;
            if (j < SEGLEN && base + j < TLEN) v = row[base + j];
            seg[fr][skew(j)] = v;
        }
    }
    __syncthreads();

    {
        const int h  = tid & 3;                 // K-chunk
        const int gg = tid >> 2;                // 0..95
        const int f  = gg / TPF;
        const int g  = gg - f * TPF;
        const float* sf = seg[f];
        const int gb = 8 * g;
        const int sb = 20 * h;                  // window-step base

        ull c0 = 0, c1 = 0, c2 = 0, c3 = 0, c4 = 0, c5 = 0, c6 = 0, c7 = 0, ns = 0;
        float4 W1;
        ull O0, O1, O2, E1, E2, E3;
        {
            float4 W0 = *reinterpret_cast<const float4*>(sf + skew(gb + 4 * sb));
            W1        = *reinterpret_cast<const float4*>(sf + skew(gb + 4 * sb + 4));
            O0 = pk(W0.y, W0.z); O1 = pk(W0.w, W1.x); O2 = pk(W1.y, W1.z);
            E1 = pk(W0.z, W0.w); E2 = pk(W1.x, W1.y); E3 = pk(W1.z, W1.w);
        }

        #pragma unroll 5
        for (int s = 0; s < 20; s++) {
            float4 Aq = *reinterpret_cast<const float4*>(sf + skew(4 * (sb + s)));
            ull A01 = pk(Aq.x, Aq.y);
            ull A23 = pk(Aq.z, Aq.w);
            float4 W2 = *reinterpret_cast<const float4*>(sf + skew(gb + 8 + 4 * (sb + s)));

            ull O3 = pk(W1.w, W2.x);
            ull E4 = pk(W2.x, W2.y);
            ull O4 = pk(W2.y, W2.z);
            ull E5 = pk(W2.z, W2.w);

            ffma2(c0, A01, O0); ffma2(c0, A23, O1);
            ffma2(c1, A01, E1); ffma2(c1, A23, E2);
            ffma2(c2, A01, O1); ffma2(c2, A23, O2);
            ffma2(c3, A01, E2); ffma2(c3, A23, E3);
            ffma2(c4, A01, O2); ffma2(c4, A23, O3);
            ffma2(c5, A01, E3); ffma2(c5, A23, E4);
            ffma2(c6, A01, O3); ffma2(c6, A23, O4);
            ffma2(c7, A01, E4); ffma2(c7, A23, E5);
            ffma2(ns, O0, O0);  ffma2(ns, O1, O1);

            O0 = O2; O1 = O3; O2 = O4;
            E1 = E3; E2 = E4; E3 = E5;
            W1 = W2;
        }

        // Reduce packed pairs to scalars, then combine K-partials via shfl.
        float cr[8], nsum;
        { float lo, hi;
          upk(lo, hi, c0); cr[0] = lo + hi; upk(lo, hi, c1); cr[1] = lo + hi;
          upk(lo, hi, c2); cr[2] = lo + hi; upk(lo, hi, c3); cr[3] = lo + hi;
          upk(lo, hi, c4); cr[4] = lo + hi; upk(lo, hi, c5); cr[5] = lo + hi;
          upk(lo, hi, c6); cr[6] = lo + hi; upk(lo, hi, c7); cr[7] = lo + hi;
          upk(lo, hi, ns); nsum  = lo + hi; }
        #pragma unroll
        for (int d = 1; d <= 2; d <<= 1) {
            #pragma unroll
            for (int l = 0; l < 8; l++)
                cr[l] += __shfl_xor_sync(0xffffffffu, cr[l], d);
            nsum += __shfl_xor_sync(0xffffffffu, nsum, d);
        }

        // norms: n2[0] = nsum, n2[l] via endpoint fixups
        float n2[8];
        n2[0] = nsum;
        #pragma unroll
        for (int l = 1; l < 8; l++) {
            float xa = sf[skew(gb + l)];
            float xb = sf[skew(gb + 320 + l)];
            n2[l] = n2[l - 1] - xa * xa + xb * xb;
        }
        // each h-thread writes 2 of the 8 lags (fast div: feeds comparisons only)
        #pragma unroll
        for (int l = 2 * h; l < 2 * h + 2; l++) {
            float d = EPSF + sqrtf(n2[l]);
            sval[f][gb + l] = __fdividef(cr[l], d * d);
        }

        if (g == 0 && h == 0) {  // energy = (n2[0] + seg[0]^2 - seg[320]^2)/320
            float x0 = sf[skew(0)], x3 = sf[skew(320)];
            out[OFF_ENERGY + fr0 + f] = (n2[0] + x0 * x0 - x3 * x3) * (1.0f / FRAME);
        }
    }
    __syncthreads();

    // Argmax per frame: warps 0..3 handle frames 0..3 (first-occurrence)
    if (warp < FPB) {
        const float* sv = sval[warp];
        float bv = -3.0e38f; int bi = 1 << 30;
        float hv = -3.0e38f; int hi = 1 << 30;
        for (int t = LAG_MIN + lane; t < LAGS; t += 32) {
            float x = sv[t];
            if (x > bv) { bv = x; bi = t; }
            if (t < HALFSZ && x > hv) { hv = x; hi = t; }
        }
        #pragma unroll
        for (int off = 16; off; off >>= 1) {
            float ov  = __shfl_down_sync(0xffffffffu, bv, off);
            int   oi  = __shfl_down_sync(0xffffffffu, bi, off);
            if (ov > bv || (ov == bv && oi < bi)) { bv = ov; bi = oi; }
            float ohv = __shfl_down_sync(0xffffffffu, hv, off);
            int   ohi = __shfl_down_sync(0xffffffffu, hi, off);
            if (ohv > hv || (ohv == hv && ohi < hi)) { hv = ohv; hi = ohi; }
        }
        if (lane == 0) {
            int sel = (hv > 0.99f * bv) ? hi : bi;
            g_idx[fr0 + warp] = sel + 1;
        }
    }
}

// ---------------------------------------------------------------------------
// Kernel 2 (8-CTA cluster): CTA b computes batch row b's medians -> f0/voiced,
// then after a cluster barrier every CTA computes the global mean/std over
// all 1880 f0 values (redundantly, symmetric) and writes its whiten slice.
// Median counts directly from a left-padded smem row (no register spill).
// ---------------------------------------------------------------------------
__global__ void __launch_bounds__(256) __cluster_dims__(BATCH, 1, 1)
median_stats_kernel(float* __restrict__ out) {
    const int b = blockIdx.x;
    const int tid = threadIdx.x;
    __shared__ int   row[PADM + KFRM];
    __shared__ float f0s[BATCH * NOUT];
    __shared__ float red[256];

    for (int t = tid; t < PADM + KFRM; t += 256) {
        int p = t - PADM;
        row[t] = g_idx[b * KFRM + (p < 0 ? 0 : p)];
    }
    __syncthreads();

    if (tid < NOUT) {
        const int* w = row + tid;
        // rank-14 (0-based) = smallest x with count(w <= x) >= 15
        int lo = 1, hi = LAGS + 1;   // width 189 -> 8 halvings reach 0
        #pragma unroll
        for (int it = 0; it < 8; it++) {
            int mid = (lo + hi) >> 1;
            int cnt = 0;
            #pragma unroll
            for (int m = 0; m < WINMED; m++) cnt += (w[m] <= mid);
            if (cnt >= PADM + 1) hi = mid; else lo = mid + 1;
        }
        float f0 = 16000.0f / (1e-9f + (float)lo);
        out[OFF_F0 + b * NOUT + tid]     = f0;
        out[OFF_VOICED + b * NOUT + tid] = 1.0f;   // idx >= 6 -> f0 > 0 always
    }
    __threadfence();  // make this CTA's f0 visible device-wide
    __syncthreads();
    asm volatile("barrier.cluster.arrive.aligned;" ::: "memory");
    asm volatile("barrier.cluster.wait.aligned;"   ::: "memory");

    // Every CTA: stats over all f0 (two-pass, matches reference formulation)
    const int N = BATCH * NOUT;  // 1880
    float s = 0.0f;
    for (int i = tid; i < N; i += 256) {
        float v = out[OFF_F0 + i];
        f0s[i] = v;
        s += v;
    }
    red[tid] = s;
    __syncthreads();
    #pragma unroll
    for (int off = 128; off; off >>= 1) {
        if (tid < off) red[tid] += red[tid + off];
        __syncthreads();
    }
    float mean = red[0] / (float)N;
    __syncthreads();

    float s2 = 0.0f;
    for (int i = tid; i < N; i += 256) {
        float d = f0s[i] - mean;
        s2 = fmaf(d, d, s2);
    }
    red[tid] = s2;
    __syncthreads();
    #pragma unroll
    for (int off = 128; off; off >>= 1) {
        if (tid < off) red[tid] += red[tid + off];
        __syncthreads();
    }
    float sd = sqrtf(red[0] / (float)(N - 1));
    if (sd == 0.0f) sd = 1.0f;
    float inv = 1.0f / sd;

    // write own slice of whiten
    if (tid < NOUT) {
        int n = b * NOUT + tid;
        out[OFF_WHITEN + n] = (f0s[n] - mean) * inv;
    }
}

extern "C" void kernel_launch(void* const* d_in, const int* in_sizes, int n_in,
                              void* d_out, int out_size) {
    const float* audio = (const float*)d_in[0];
    float* out = (float*)d_out;
    (void)in_sizes; (void)n_in; (void)out_size;

    nccf_kernel<<<(BATCH * KFRM) / FPB, NTHR>>>(audio, out);
    median_stats_kernel<<<BATCH, 256>>>(out);   // launches as one 8-CTA cluster
}

// round 8
// speedup vs baseline: 1.3799x; 1.1772x over previous
#include <cuda_runtime.h>
#include <cstdint>

// Problem constants (fixed by setup_inputs: audio (8, 80000) fp32)
#define BATCH   8
#define TLEN    80000
#define KFRM    250
#define FRAME   320
#define LAGS    189
#define LAG_MIN 5
#define HALFSZ  94             // LAGS // 2
#define SEGLEN  509            // FRAME + LAGS
#define NOUT    235
#define WINMED  30
#define PADM    14
#define EPSF    1e-9f

// nccf kernel blocking
#define TPF   24               // lag-groups per frame (8 lags each, 192 padded)
#define KSPL  4                // split-K factor (threads per lag-group)
#define FPB   4                // frames per block
#define NTHR  (FPB * TPF * KSPL)   // 384 threads, 12 warps
#define NLAGP 192
#define SEGL  520              // logical padded segment length
#define SEGP  584              // physical (skewed) words per frame

// output layout (float32): f0[B*NOUT], whiten[B*NOUT], voiced[B*NOUT], energy[B*KFRM]
#define OFF_F0     0
#define OFF_WHITEN (BATCH * NOUT)
#define OFF_VOICED (2 * BATCH * NOUT)
#define OFF_ENERGY (3 * BATCH * NOUT)

__device__ int g_idx[BATCH * KFRM];

typedef unsigned long long ull;

__device__ __forceinline__ int skew(int m) { return m + ((m >> 5) << 2); }

__device__ __forceinline__ ull pk(float lo, float hi) {
    ull r; asm("mov.b64 %0, {%1, %2};" : "=l"(r) : "f"(lo), "f"(hi)); return r;
}
__device__ __forceinline__ void upk(float& lo, float& hi, ull v) {
    asm("mov.b64 {%0, %1}, %2;" : "=f"(lo), "=f"(hi) : "l"(v));
}
__device__ __forceinline__ void ffma2(ull& d, ull a, ull b) {
    asm("fma.rn.f32x2 %0, %1, %2, %0;" : "+l"(d) : "l"(a), "l"(b));
}

// ---------------------------------------------------------------------------
// Kernel 1: NCCF + argmax + energy. 4 frames/block, 384 threads, grid 500.
// Thread (f, g, h): lags 8g..8g+7 over K-chunk h (window steps 20h..20h+19),
// sliding register window, packed f32x2 FMAs. Mainloop FULLY UNROLLED so
// ptxas renames the window registers across iterations (no rotation MOVs).
// The 4 K-partials combine via 2 shfl_xor rounds; norms from one running
// sum + endpoint fixups.
// ---------------------------------------------------------------------------
__global__ void __launch_bounds__(NTHR) nccf_kernel(const float* __restrict__ audio,
                                                    float* __restrict__ out) {
    __shared__ __align__(16) float seg[FPB][SEGP];
    __shared__ float sval[FPB][NLAGP];

    const int tid  = threadIdx.x;
    const int warp = tid >> 5;
    const int lane = tid & 31;
    const int fr0  = blockIdx.x * FPB;

    // Stage: 12 warps, 3 warps per frame (skewed layout, zero-padded)
    {
        const int fr   = warp & 3;
        const int part = warp >> 2;       // 0..2
        const int gfr  = fr0 + fr;
        const int b    = gfr / KFRM;
        const int k    = gfr - b * KFRM;
        const float* row  = audio + (size_t)b * TLEN;
        const int    base = k * FRAME;
        for (int j = part * 32 + lane; j < SEGL; j += 96) {
            float v = 0.0f;
            if (j < SEGLEN && base + j < TLEN) v = row[base + j];
            seg[fr][skew(j)] = v;
        }
    }
    __syncthreads();

    {
        const int h  = tid & 3;                 // K-chunk
        const int gg = tid >> 2;                // 0..95
        const int f  = gg / TPF;
        const int g  = gg - f * TPF;
        const float* sf = seg[f];
        const int gb = 8 * g;
        const int sb = 20 * h;                  // window-step base

        ull c0 = 0, c1 = 0, c2 = 0, c3 = 0, c4 = 0, c5 = 0, c6 = 0, c7 = 0, ns = 0;
        float4 W1;
        ull O0, O1, O2, E1, E2, E3;
        {
            float4 W0 = *reinterpret_cast<const float4*>(sf + skew(gb + 4 * sb));
            W1        = *reinterpret_cast<const float4*>(sf + skew(gb + 4 * sb + 4));
            O0 = pk(W0.y, W0.z); O1 = pk(W0.w, W1.x); O2 = pk(W1.y, W1.z);
            E1 = pk(W0.z, W0.w); E2 = pk(W1.x, W1.y); E3 = pk(W1.z, W1.w);
        }

        #pragma unroll
        for (int s = 0; s < 20; s++) {
            float4 Aq = *reinterpret_cast<const float4*>(sf + skew(4 * (sb + s)));
            ull A01 = pk(Aq.x, Aq.y);
            ull A23 = pk(Aq.z, Aq.w);
            float4 W2 = *reinterpret_cast<const float4*>(sf + skew(gb + 8 + 4 * (sb + s)));

            ull O3 = pk(W1.w, W2.x);
            ull E4 = pk(W2.x, W2.y);
            ull O4 = pk(W2.y, W2.z);
            ull E5 = pk(W2.z, W2.w);

            ffma2(c0, A01, O0); ffma2(c0, A23, O1);
            ffma2(c1, A01, E1); ffma2(c1, A23, E2);
            ffma2(c2, A01, O1); ffma2(c2, A23, O2);
            ffma2(c3, A01, E2); ffma2(c3, A23, E3);
            ffma2(c4, A01, O2); ffma2(c4, A23, O3);
            ffma2(c5, A01, E3); ffma2(c5, A23, E4);
            ffma2(c6, A01, O3); ffma2(c6, A23, O4);
            ffma2(c7, A01, E4); ffma2(c7, A23, E5);
            ffma2(ns, O0, O0);  ffma2(ns, O1, O1);

            O0 = O2; O1 = O3; O2 = O4;
            E1 = E3; E2 = E4; E3 = E5;
            W1 = W2;
        }

        // Reduce packed pairs to scalars, then combine K-partials via shfl.
        float cr[8], nsum;
        { float lo, hi;
          upk(lo, hi, c0); cr[0] = lo + hi; upk(lo, hi, c1); cr[1] = lo + hi;
          upk(lo, hi, c2); cr[2] = lo + hi; upk(lo, hi, c3); cr[3] = lo + hi;
          upk(lo, hi, c4); cr[4] = lo + hi; upk(lo, hi, c5); cr[5] = lo + hi;
          upk(lo, hi, c6); cr[6] = lo + hi; upk(lo, hi, c7); cr[7] = lo + hi;
          upk(lo, hi, ns); nsum  = lo + hi; }
        #pragma unroll
        for (int d = 1; d <= 2; d <<= 1) {
            #pragma unroll
            for (int l = 0; l < 8; l++)
                cr[l] += __shfl_xor_sync(0xffffffffu, cr[l], d);
            nsum += __shfl_xor_sync(0xffffffffu, nsum, d);
        }

        // norms: n2[0] = nsum, n2[l] via endpoint fixups
        float n2[8];
        n2[0] = nsum;
        #pragma unroll
        for (int l = 1; l < 8; l++) {
            float xa = sf[skew(gb + l)];
            float xb = sf[skew(gb + 320 + l)];
            n2[l] = n2[l - 1] - xa * xa + xb * xb;
        }
        // each h-thread writes 2 of the 8 lags (fast div: feeds comparisons only)
        #pragma unroll
        for (int l = 2 * h; l < 2 * h + 2; l++) {
            float d = EPSF + sqrtf(n2[l]);
            sval[f][gb + l] = __fdividef(cr[l], d * d);
        }

        if (g == 0 && h == 0) {  // energy = (n2[0] + seg[0]^2 - seg[320]^2)/320
            float x0 = sf[skew(0)], x3 = sf[skew(320)];
            out[OFF_ENERGY + fr0 + f] = (n2[0] + x0 * x0 - x3 * x3) * (1.0f / FRAME);
        }
    }
    __syncthreads();

    // Argmax per frame: warps 0..3 handle frames 0..3 (first-occurrence)
    if (warp < FPB) {
        const float* sv = sval[warp];
        float bv = -3.0e38f; int bi = 1 << 30;
        float hv = -3.0e38f; int hi = 1 << 30;
        for (int t = LAG_MIN + lane; t < LAGS; t += 32) {
            float x = sv[t];
            if (x > bv) { bv = x; bi = t; }
            if (t < HALFSZ && x > hv) { hv = x; hi = t; }
        }
        #pragma unroll
        for (int off = 16; off; off >>= 1) {
            float ov  = __shfl_down_sync(0xffffffffu, bv, off);
            int   oi  = __shfl_down_sync(0xffffffffu, bi, off);
            if (ov > bv || (ov == bv && oi < bi)) { bv = ov; bi = oi; }
            float ohv = __shfl_down_sync(0xffffffffu, hv, off);
            int   ohi = __shfl_down_sync(0xffffffffu, hi, off);
            if (ohv > hv || (ohv == hv && ohi < hi)) { hv = ohv; hi = ohi; }
        }
        if (lane == 0) {
            int sel = (hv > 0.99f * bv) ? hi : bi;
            g_idx[fr0 + warp] = sel + 1;
        }
    }
}

// ---------------------------------------------------------------------------
// Kernel 2 (8-CTA cluster): CTA b computes batch row b's medians -> f0 in
// LOCAL smem (+ f0/voiced to global), reduces row partial sums (s1, s2),
// pushes the 8-byte pair to every peer CTA's smem slot via mapa/st.cluster,
// cluster-syncs, then each CTA combines the 8 slots in fixed order (exact
// determinism) and writes its own whiten slice. No global round trip,
// no __threadfence.
// ---------------------------------------------------------------------------
__global__ void __launch_bounds__(256) __cluster_dims__(BATCH, 1, 1)
median_stats_kernel(float* __restrict__ out) {
    const int b = blockIdx.x;
    const int tid = threadIdx.x;
    __shared__ int    row[PADM + KFRM];
    __shared__ float  f0row[NOUT];
    __shared__ float  wred[8][2];
    __shared__ __align__(8) float slots[BATCH][2];   // same offset in every CTA

    for (int t = tid; t < PADM + KFRM; t += 256) {
        int p = t - PADM;
        row[t] = g_idx[b * KFRM + (p < 0 ? 0 : p)];
    }
    __syncthreads();

    float f0 = 0.0f;
    if (tid < NOUT) {
        const int* w = row + tid;
        // rank-14 (0-based) = smallest x with count(w <= x) >= 15
        int lo = 1, hi = LAGS + 1;
        #pragma unroll
        for (int it = 0; it < 8; it++) {
            int mid = (lo + hi) >> 1;
            int cnt = 0;
            #pragma unroll
            for (int m = 0; m < WINMED; m++) cnt += (w[m] <= mid);
            if (cnt >= PADM + 1) hi = mid; else lo = mid + 1;
        }
        f0 = 16000.0f / (1e-9f + (float)lo);
        f0row[tid] = f0;
        out[OFF_F0 + b * NOUT + tid]     = f0;
        out[OFF_VOICED + b * NOUT + tid] = 1.0f;   // idx >= 6 -> f0 > 0 always
    }

    // Row partial sums s1 = sum f0, s2 = sum f0^2 (fixed reduction order)
    float s1 = f0, s2 = f0 * f0;
    #pragma unroll
    for (int off = 16; off; off >>= 1) {
        s1 += __shfl_down_sync(0xffffffffu, s1, off);
        s2 += __shfl_down_sync(0xffffffffu, s2, off);
    }
    if ((tid & 31) == 0) { wred[tid >> 5][0] = s1; wred[tid >> 5][1] = s2; }
    __syncthreads();

    if (tid == 0) {
        float t1 = 0.0f, t2 = 0.0f;
        #pragma unroll
        for (int wv = 0; wv < 8; wv++) { t1 += wred[wv][0]; t2 += wred[wv][1]; }
        // push (t1, t2) into slot[b] of every CTA (including self)
        ull pair; asm("mov.b64 %0, {%1, %2};" : "=l"(pair) : "f"(t1), "f"(t2));
        unsigned int laddr;
        asm("{ .reg .u64 a; cvta.to.shared.u64 a, %1; cvt.u32.u64 %0, a; }"
            : "=r"(laddr) : "l"(&slots[b][0]));
        #pragma unroll
        for (int p = 0; p < BATCH; p++) {
            unsigned int raddr;
            asm("mapa.shared::cluster.u32 %0, %1, %2;" : "=r"(raddr) : "r"(laddr), "r"(p));
            asm volatile("st.shared::cluster.b64 [%0], %1;" :: "r"(raddr), "l"(pair) : "memory");
        }
    }
    __syncthreads();
    asm volatile("barrier.cluster.arrive.aligned;" ::: "memory");
    asm volatile("barrier.cluster.wait.aligned;"   ::: "memory");

    // Combine the 8 slots in fixed order -> identical mean/std in every CTA
    const float N = (float)(BATCH * NOUT);   // 1880
    float g1 = 0.0f, g2 = 0.0f;
    #pragma unroll
    for (int p = 0; p < BATCH; p++) { g1 += slots[p][0]; g2 += slots[p][1]; }
    float mean = g1 / N;
    // sum (f0-mean)^2 = g2 - 2*mean*g1 + N*mean^2
    float ssq = g2 - 2.0f * mean * g1 + N * mean * mean;
    float sd  = sqrtf(ssq / (N - 1.0f));
    if (sd == 0.0f) sd = 1.0f;
    float inv = 1.0f / sd;

    if (tid < NOUT)
        out[OFF_WHITEN + b * NOUT + tid] = (f0row[tid] - mean) * inv;
}

extern "C" void kernel_launch(void* const* d_in, const int* in_sizes, int n_in,
                              void* d_out, int out_size) {
    const float* audio = (const float*)d_in[0];
    float* out = (float*)d_out;
    (void)in_sizes; (void)n_in; (void)out_size;

    nccf_kernel<<<(BATCH * KFRM) / FPB, NTHR>>>(audio, out);
    median_stats_kernel<<<BATCH, 256>>>(out);   // launches as one 8-CTA cluster
}

// round 9
// speedup vs baseline: 1.4009x; 1.0152x over previous
#include <cuda_runtime.h>
#include <cstdint>

// Problem constants (fixed by setup_inputs: audio (8, 80000) fp32)
#define BATCH   8
#define TLEN    80000
#define KFRM    250
#define FRAME   320
#define LAGS    189
#define LAG_MIN 5
#define HALFSZ  94             // LAGS // 2
#define SEGLEN  509            // FRAME + LAGS
#define NOUT    235
#define WINMED  30
#define PADM    14
#define EPSF    1e-9f

// nccf kernel blocking: ONE frame per block, 96 threads (3 warps), grid 2000
#define TPF   24               // lag-groups per frame (8 lags each, 192 padded)
#define KSPL  4                // split-K factor (threads per lag-group)
#define NTHR  (TPF * KSPL)     // 96 threads
#define NLAGP 192
#define SEGL  520              // logical padded segment length
#define SEGP  584              // physical (skewed) words per frame

// output layout (float32): f0[B*NOUT], whiten[B*NOUT], voiced[B*NOUT], energy[B*KFRM]
#define OFF_F0     0
#define OFF_WHITEN (BATCH * NOUT)
#define OFF_VOICED (2 * BATCH * NOUT)
#define OFF_ENERGY (3 * BATCH * NOUT)

__device__ int g_idx[BATCH * KFRM];

typedef unsigned long long ull;

__device__ __forceinline__ int skew(int m) { return m + ((m >> 5) << 2); }

__device__ __forceinline__ ull pk(float lo, float hi) {
    ull r; asm("mov.b64 %0, {%1, %2};" : "=l"(r) : "f"(lo), "f"(hi)); return r;
}
__device__ __forceinline__ void upk(float& lo, float& hi, ull v) {
    asm("mov.b64 {%0, %1}, %2;" : "=f"(lo), "=f"(hi) : "l"(v));
}
__device__ __forceinline__ void ffma2(ull& d, ull a, ull b) {
    asm("fma.rn.f32x2 %0, %1, %2, %0;" : "+l"(d) : "l"(a), "l"(b));
}

// ---------------------------------------------------------------------------
// Kernel 1: NCCF + argmax + energy. ONE frame per block, 96 threads, grid
// 2000 -> ~13.5 blocks/SM: fine-grained balance + high occupancy for latency
// hiding. Thread (g, h): lags 8g..8g+7 over K-chunk h (window steps
// 20h..20h+19), sliding register window, packed f32x2 FMAs, mainloop fully
// unrolled. 4 K-partials combine via 2 shfl_xor rounds (h = tid&3 in-warp);
// norms from one running sum + endpoint fixups.
// ---------------------------------------------------------------------------
__global__ void __launch_bounds__(NTHR) nccf_kernel(const float* __restrict__ audio,
                                                    float* __restrict__ out) {
    __shared__ __align__(16) float seg[SEGP];
    __shared__ float sval[NLAGP];

    const int tid  = threadIdx.x;
    const int warp = tid >> 5;
    const int lane = tid & 31;
    const int fr   = blockIdx.x;           // frame id = b*KFRM + k

    // Stage this frame (skewed layout, zero-padded)
    {
        const int b = fr / KFRM;
        const int k = fr - b * KFRM;
        const float* row  = audio + (size_t)b * TLEN;
        const int    base = k * FRAME;
        for (int j = tid; j < SEGL; j += NTHR) {
            float v = 0.0f;
            if (j < SEGLEN && base + j < TLEN) v = row[base + j];
            seg[skew(j)] = v;
        }
    }
    __syncthreads();

    {
        const int h  = tid & 3;                 // K-chunk
        const int g  = tid >> 2;                // lag-group 0..23
        const float* sf = seg;
        const int gb = 8 * g;
        const int sb = 20 * h;                  // window-step base

        ull c0 = 0, c1 = 0, c2 = 0, c3 = 0, c4 = 0, c5 = 0, c6 = 0, c7 = 0, ns = 0;
        float4 W1;
        ull O0, O1, O2, E1, E2, E3;
        {
            float4 W0 = *reinterpret_cast<const float4*>(sf + skew(gb + 4 * sb));
            W1        = *reinterpret_cast<const float4*>(sf + skew(gb + 4 * sb + 4));
            O0 = pk(W0.y, W0.z); O1 = pk(W0.w, W1.x); O2 = pk(W1.y, W1.z);
            E1 = pk(W0.z, W0.w); E2 = pk(W1.x, W1.y); E3 = pk(W1.z, W1.w);
        }

        #pragma unroll
        for (int s = 0; s < 20; s++) {
            float4 Aq = *reinterpret_cast<const float4*>(sf + skew(4 * (sb + s)));
            ull A01 = pk(Aq.x, Aq.y);
            ull A23 = pk(Aq.z, Aq.w);
            float4 W2 = *reinterpret_cast<const float4*>(sf + skew(gb + 8 + 4 * (sb + s)));

            ull O3 = pk(W1.w, W2.x);
            ull E4 = pk(W2.x, W2.y);
            ull O4 = pk(W2.y, W2.z);
            ull E5 = pk(W2.z, W2.w);

            ffma2(c0, A01, O0); ffma2(c0, A23, O1);
            ffma2(c1, A01, E1); ffma2(c1, A23, E2);
            ffma2(c2, A01, O1); ffma2(c2, A23, O2);
            ffma2(c3, A01, E2); ffma2(c3, A23, E3);
            ffma2(c4, A01, O2); ffma2(c4, A23, O3);
            ffma2(c5, A01, E3); ffma2(c5, A23, E4);
            ffma2(c6, A01, O3); ffma2(c6, A23, O4);
            ffma2(c7, A01, E4); ffma2(c7, A23, E5);
            ffma2(ns, O0, O0);  ffma2(ns, O1, O1);

            O0 = O2; O1 = O3; O2 = O4;
            E1 = E3; E2 = E4; E3 = E5;
            W1 = W2;
        }

        // Reduce packed pairs to scalars, then combine K-partials via shfl.
        float cr[8], nsum;
        { float lo, hi;
          upk(lo, hi, c0); cr[0] = lo + hi; upk(lo, hi, c1); cr[1] = lo + hi;
          upk(lo, hi, c2); cr[2] = lo + hi; upk(lo, hi, c3); cr[3] = lo + hi;
          upk(lo, hi, c4); cr[4] = lo + hi; upk(lo, hi, c5); cr[5] = lo + hi;
          upk(lo, hi, c6); cr[6] = lo + hi; upk(lo, hi, c7); cr[7] = lo + hi;
          upk(lo, hi, ns); nsum  = lo + hi; }
        #pragma unroll
        for (int d = 1; d <= 2; d <<= 1) {
            #pragma unroll
            for (int l = 0; l < 8; l++)
                cr[l] += __shfl_xor_sync(0xffffffffu, cr[l], d);
            nsum += __shfl_xor_sync(0xffffffffu, nsum, d);
        }

        // norms: n2[0] = nsum, n2[l] via endpoint fixups
        float n2[8];
        n2[0] = nsum;
        #pragma unroll
        for (int l = 1; l < 8; l++) {
            float xa = sf[skew(gb + l)];
            float xb = sf[skew(gb + 320 + l)];
            n2[l] = n2[l - 1] - xa * xa + xb * xb;
        }
        // each h-thread writes 2 of the 8 lags (fast div: feeds comparisons only)
        #pragma unroll
        for (int l = 2 * h; l < 2 * h + 2; l++) {
            float d = EPSF + sqrtf(n2[l]);
            sval[gb + l] = __fdividef(cr[l], d * d);
        }

        if (tid == 0) {  // energy = (n2[0] + seg[0]^2 - seg[320]^2)/320
            float x0 = sf[skew(0)], x3 = sf[skew(320)];
            out[OFF_ENERGY + fr] = (n2[0] + x0 * x0 - x3 * x3) * (1.0f / FRAME);
        }
    }
    __syncthreads();

    // Argmax (warp 0, first-occurrence semantics)
    if (warp == 0) {
        float bv = -3.0e38f; int bi = 1 << 30;
        float hv = -3.0e38f; int hi = 1 << 30;
        for (int t = LAG_MIN + lane; t < LAGS; t += 32) {
            float x = sval[t];
            if (x > bv) { bv = x; bi = t; }
            if (t < HALFSZ && x > hv) { hv = x; hi = t; }
        }
        #pragma unroll
        for (int off = 16; off; off >>= 1) {
            float ov  = __shfl_down_sync(0xffffffffu, bv, off);
            int   oi  = __shfl_down_sync(0xffffffffu, bi, off);
            if (ov > bv || (ov == bv && oi < bi)) { bv = ov; bi = oi; }
            float ohv = __shfl_down_sync(0xffffffffu, hv, off);
            int   ohi = __shfl_down_sync(0xffffffffu, hi, off);
            if (ohv > hv || (ohv == hv && ohi < hi)) { hv = ohv; hi = ohi; }
        }
        if (lane == 0) {
            int sel = (hv > 0.99f * bv) ? hi : bi;
            g_idx[fr] = sel + 1;
        }
    }
}

// ---------------------------------------------------------------------------
// Kernel 2 (8-CTA cluster): CTA b computes batch row b's medians -> f0 in
// LOCAL smem (+ f0/voiced to global), reduces row partial sums (s1, s2),
// pushes the 8-byte pair to every peer CTA's smem slot via mapa/st.cluster,
// cluster-syncs, then each CTA combines the 8 slots in fixed order (exact
// determinism) and writes its own whiten slice.
// ---------------------------------------------------------------------------
__global__ void __launch_bounds__(256) __cluster_dims__(BATCH, 1, 1)
median_stats_kernel(float* __restrict__ out) {
    const int b = blockIdx.x;
    const int tid = threadIdx.x;
    __shared__ int    row[PADM + KFRM];
    __shared__ float  f0row[NOUT];
    __shared__ float  wred[8][2];
    __shared__ __align__(8) float slots[BATCH][2];   // same offset in every CTA

    for (int t = tid; t < PADM + KFRM; t += 256) {
        int p = t - PADM;
        row[t] = g_idx[b * KFRM + (p < 0 ? 0 : p)];
    }
    __syncthreads();

    float f0 = 0.0f;
    if (tid < NOUT) {
        const int* w = row + tid;
        // rank-14 (0-based) = smallest x with count(w <= x) >= 15
        int lo = 1, hi = LAGS + 1;
        #pragma unroll
        for (int it = 0; it < 8; it++) {
            int mid = (lo + hi) >> 1;
            int cnt = 0;
            #pragma unroll
            for (int m = 0; m < WINMED; m++) cnt += (w[m] <= mid);
            if (cnt >= PADM + 1) hi = mid; else lo = mid + 1;
        }
        f0 = 16000.0f / (1e-9f + (float)lo);
        f0row[tid] = f0;
        out[OFF_F0 + b * NOUT + tid]     = f0;
        out[OFF_VOICED + b * NOUT + tid] = 1.0f;   // idx >= 6 -> f0 > 0 always
    }

    // Row partial sums s1 = sum f0, s2 = sum f0^2 (fixed reduction order)
    float s1 = f0, s2 = f0 * f0;
    #pragma unroll
    for (int off = 16; off; off >>= 1) {
        s1 += __shfl_down_sync(0xffffffffu, s1, off);
        s2 += __shfl_down_sync(0xffffffffu, s2, off);
    }
    if ((tid & 31) == 0) { wred[tid >> 5][0] = s1; wred[tid >> 5][1] = s2; }
    __syncthreads();

    if (tid == 0) {
        float t1 = 0.0f, t2 = 0.0f;
        #pragma unroll
        for (int wv = 0; wv < 8; wv++) { t1 += wred[wv][0]; t2 += wred[wv][1]; }
        ull pair; asm("mov.b64 %0, {%1, %2};" : "=l"(pair) : "f"(t1), "f"(t2));
        unsigned int laddr;
        asm("{ .reg .u64 a; cvta.to.shared.u64 a, %1; cvt.u32.u64 %0, a; }"
            : "=r"(laddr) : "l"(&slots[b][0]));
        #pragma unroll
        for (int p = 0; p < BATCH; p++) {
            unsigned int raddr;
            asm("mapa.shared::cluster.u32 %0, %1, %2;" : "=r"(raddr) : "r"(laddr), "r"(p));
            asm volatile("st.shared::cluster.b64 [%0], %1;" :: "r"(raddr), "l"(pair) : "memory");
        }
    }
    __syncthreads();
    asm volatile("barrier.cluster.arrive.aligned;" ::: "memory");
    asm volatile("barrier.cluster.wait.aligned;"   ::: "memory");

    // Combine the 8 slots in fixed order -> identical mean/std in every CTA
    const float N = (float)(BATCH * NOUT);   // 1880
    float g1 = 0.0f, g2 = 0.0f;
    #pragma unroll
    for (int p = 0; p < BATCH; p++) { g1 += slots[p][0]; g2 += slots[p][1]; }
    float mean = g1 / N;
    float ssq = g2 - 2.0f * mean * g1 + N * mean * mean;   // == sum (f0-mean)^2
    float sd  = sqrtf(ssq / (N - 1.0f));
    if (sd == 0.0f) sd = 1.0f;
    float inv = 1.0f / sd;

    if (tid < NOUT)
        out[OFF_WHITEN + b * NOUT + tid] = (f0row[tid] - mean) * inv;
}

extern "C" void kernel_launch(void* const* d_in, const int* in_sizes, int n_in,
                              void* d_out, int out_size) {
    const float* audio = (const float*)d_in[0];
    float* out = (float*)d_out;
    (void)in_sizes; (void)n_in; (void)out_size;

    nccf_kernel<<<BATCH * KFRM, NTHR>>>(audio, out);
    median_stats_kernel<<<BATCH, 256>>>(out);   // launches as one 8-CTA cluster
}